// round 4
// baseline (speedup 1.0000x reference)
#include <cuda_runtime.h>
#include <cuda_fp16.h>

// Problem constants
#define DVOL 160
#define HWS  25600            // 160*160
#define VOL  4096000          // 160^3
#define NTOT 8192000          // 2 * 160^3

#define K1_BLOCKS 8000        // 5*5*320
#define K2_BLOCKS 1600        // 200*8
#define DSEG 20               // depth segment length in k2

// Packed intermediates (fp16):
//   g_A[idx]   = half2(blur(p), blur(t))
//   g_B[idx].x = half2(blur(p*p), blur(t*t));  .y = half2(blur(p*t), 0)
__device__ unsigned int g_A[NTOT];
__device__ uint2        g_B[NTOT];
__device__ float g_l1_part[K1_BLOCKS];
__device__ float g_ssim_part[K2_BLOCKS];

// Gaussian weights (size 11, sigma 1.5, normalized) as literals so ptxas
// emits FFMA-imm (rt_SMSP=1 instead of 2).
#define GW_INIT {0.00102838f, 0.00759876f, 0.03600078f, 0.10936070f, \
                 0.21300554f, 0.26601172f, 0.21300554f, 0.10936070f, \
                 0.03600078f, 0.00759876f, 0.00102838f}

// ---------------------------------------------------------------------------
// Kernel 1: per (n,d) slice, fused W-blur + H-blur of the 5 product channels,
// 32x32 output tiles, packed fp16 output + per-block L1 partial.
// ---------------------------------------------------------------------------
__global__ __launch_bounds__(256, 3) void k_blur_wh(
    const float* __restrict__ pred, const float* __restrict__ tgt)
{
    __shared__ float2 rpt[42][45];        // raw tile, pitch 45 (conflict-free LDS.64)
    __shared__ float4 stA4[42][33];       // W-blurred ch 0..3, pitch 33
    __shared__ float  stA1[42][33];       // W-blurred ch 4
    __shared__ float  red[8];

    const float GW[11] = GW_INIT;

    const int bz = blockIdx.z;            // n*160 + d
    const int n  = bz / DVOL;
    const int d  = bz % DVOL;
    const int h0 = blockIdx.y * 32;
    const int w0 = blockIdx.x * 32;
    const int base = n * VOL + d * HWS;
    const int tid = threadIdx.x;

    // --- load raw 42x42 halo region (zero padded) -------------------------
    {
        int r = tid / 42;
        int c = tid - r * 42;
        while (r < 42) {
            const int gh = h0 - 5 + r;
            const int gw = w0 - 5 + c;
            float p = 0.f, t = 0.f;
            if ((unsigned)gh < 160u && (unsigned)gw < 160u) {
                const int idx = base + gh * DVOL + gw;
                p = pred[idx];
                t = tgt[idx];
            }
            rpt[r][c] = make_float2(p, t);
            r += 6; c += 4;                  // advance by 256 = 6*42 + 4
            if (c >= 42) { c -= 42; r += 1; }
        }
    }
    __syncthreads();

    // --- L1 partial over the 32x32 interior -------------------------------
    float l1 = 0.f;
#pragma unroll
    for (int k = 0; k < 4; k++) {
        const int i = tid + k * 256;
        const int hh = i >> 5, ww = i & 31;
        const float2 v = rpt[5 + hh][5 + ww];
        l1 += fabsf(v.x - v.y);
    }

    // --- phase A: blur along W with register rings ------------------------
    // thread = (row r in 0..41, col-group g in 0..5), each group covers 6 cols
    if (tid < 252) {
        const int g = tid / 42;
        const int r = tid - 42 * g;
        const int c0 = g * 6;

        float qp[11], qt[11], qpp[11], qtt[11], qpt[11];
#pragma unroll
        for (int k = 0; k < 10; k++) {
            const float2 v = rpt[r][c0 + k];
            qp[k] = v.x; qt[k] = v.y;
            qpp[k] = v.x * v.x; qtt[k] = v.y * v.y; qpt[k] = v.x * v.y;
        }
#pragma unroll
        for (int s = 0; s < 6; s++) {
            const int c = c0 + s;
            if (c < 32) {
                const float2 v = rpt[r][c + 10];
                const int sl = (s + 10) % 11;
                qp[sl] = v.x; qt[sl] = v.y;
                qpp[sl] = v.x * v.x; qtt[sl] = v.y * v.y; qpt[sl] = v.x * v.y;
                float a0 = 0.f, a1 = 0.f, a2 = 0.f, a3 = 0.f, a4 = 0.f;
#pragma unroll
                for (int j = 0; j < 11; j++) {
                    const int q = (s + j) % 11;
                    const float w = GW[j];
                    a0 += w * qp[q];
                    a1 += w * qt[q];
                    a2 += w * qpp[q];
                    a3 += w * qtt[q];
                    a4 += w * qpt[q];
                }
                stA4[r][c] = make_float4(a0, a1, a2, a3);
                stA1[r][c] = a4;
            }
        }
    }

    // reduce L1 (warp shuffles, then smem) — overlaps with phase A compute
#pragma unroll
    for (int o = 16; o; o >>= 1) l1 += __shfl_down_sync(0xffffffffu, l1, o);
    if ((tid & 31) == 0) red[tid >> 5] = l1;

    __syncthreads();   // stA ready + red ready

    if (tid == 0) {
        float s = 0.f;
#pragma unroll
        for (int k = 0; k < 8; k++) s += red[k];
        const int bidlin = blockIdx.x + 5 * (blockIdx.y + 5 * blockIdx.z);
        g_l1_part[bidlin] = s;
    }

    // --- phase B: blur along H, pack fp16, store directly ------------------
    // thread = (hgroup hg in 0..7, col ww in 0..31), 4 outputs per thread.
    {
        const int ww = tid & 31;
        const int hg = tid >> 5;          // 0..7
        const int rbase = hg * 4;

        float acc[4][5];
#pragma unroll
        for (int o = 0; o < 4; o++)
#pragma unroll
            for (int c = 0; c < 5; c++) acc[o][c] = 0.f;

#pragma unroll
        for (int rr = 0; rr < 14; rr++) {
            const float4 f4 = stA4[rbase + rr][ww];
            const float  f1 = stA1[rbase + rr][ww];
#pragma unroll
            for (int o = 0; o < 4; o++) {
                const int j = rr - o;
                if (j >= 0 && j <= 10) {
                    const float w = GW[j];
                    acc[o][0] += w * f4.x;
                    acc[o][1] += w * f4.y;
                    acc[o][2] += w * f4.z;
                    acc[o][3] += w * f4.w;
                    acc[o][4] += w * f1;
                }
            }
        }

#pragma unroll
        for (int o = 0; o < 4; o++) {
            const int hh = rbase + o;
            const int idx = base + (h0 + hh) * DVOL + w0 + ww;
            const __half2 ha = __floats2half2_rn(acc[o][0], acc[o][1]);
            const __half2 hb = __floats2half2_rn(acc[o][2], acc[o][3]);
            const __half2 hc = __floats2half2_rn(acc[o][4], 0.f);
            g_A[idx] = *(const unsigned int*)&ha;
            uint2 vb;
            vb.x = *(const unsigned int*)&hb;
            vb.y = *(const unsigned int*)&hc;
            g_B[idx] = vb;
        }
    }
}

// ---------------------------------------------------------------------------
// Kernel 2: blur along D (register ring, unroll-by-11), SSIM map, per-block
// reduction. grid: (51200/256, 8) — 8 depth segments of 20 for occupancy.
// ---------------------------------------------------------------------------
__global__ __launch_bounds__(256) void k_blur_d_ssim()
{
    const float GW[11] = GW_INIT;
    const int col = blockIdx.x * 256 + threadIdx.x;   // 0..51199
    const int n  = col / HWS;
    const int hw = col - n * HWS;
    const int dstart = blockIdx.y * DSEG;
    const int base = n * VOL + hw;

    float rg[5][11];
#pragma unroll
    for (int c = 0; c < 5; c++)
#pragma unroll
        for (int k = 0; k < 11; k++) rg[c][k] = 0.f;

    // preload depths dstart-5 .. dstart+4 into slots 0..9
#pragma unroll
    for (int k = 0; k < 10; k++) {
        const int dep = dstart - 5 + k;
        if (dep >= 0) {
            const int idx = base + dep * HWS;
            const unsigned int a = g_A[idx];
            const uint2 b = g_B[idx];
            const float2 f01 = __half22float2(*(const __half2*)&a);
            const float2 f23 = __half22float2(*(const __half2*)&b.x);
            const float2 f4  = __half22float2(*(const __half2*)&b.y);
            rg[0][k] = f01.x; rg[1][k] = f01.y;
            rg[2][k] = f23.x; rg[3][k] = f23.y;
            rg[4][k] = f4.x;
        }
    }

    float ssim_acc = 0.f;
    for (int s0 = 0; s0 < 22; s0 += 11) {
#pragma unroll
        for (int u = 0; u < 11; u++) {
            const int s = s0 + u;
            if (s < DSEG) {
                const int dep = dstart + s + 5;
                const int sl = (u + 10) % 11;
                if (dep < DVOL) {
                    const int idx = base + dep * HWS;
                    const unsigned int a = g_A[idx];
                    const uint2 b = g_B[idx];
                    const float2 f01 = __half22float2(*(const __half2*)&a);
                    const float2 f23 = __half22float2(*(const __half2*)&b.x);
                    const float2 f4  = __half22float2(*(const __half2*)&b.y);
                    rg[0][sl] = f01.x; rg[1][sl] = f01.y;
                    rg[2][sl] = f23.x; rg[3][sl] = f23.y;
                    rg[4][sl] = f4.x;
                } else {
#pragma unroll
                    for (int c = 0; c < 5; c++) rg[c][sl] = 0.f;
                }
                float mu1 = 0.f, mu2 = 0.f, e11 = 0.f, e22 = 0.f, e12 = 0.f;
#pragma unroll
                for (int j = 0; j < 11; j++) {
                    const int q = (u + j) % 11;
                    const float w = GW[j];
                    mu1 += w * rg[0][q];
                    mu2 += w * rg[1][q];
                    e11 += w * rg[2][q];
                    e22 += w * rg[3][q];
                    e12 += w * rg[4][q];
                }
                const float mu1sq = mu1 * mu1;
                const float mu2sq = mu2 * mu2;
                const float mu12  = mu1 * mu2;
                const float s1  = e11 - mu1sq;
                const float s2  = e22 - mu2sq;
                const float s12 = e12 - mu12;
                const float C1 = 1e-4f, C2 = 9e-4f;
                const float num = (2.f * mu12 + C1) * (2.f * s12 + C2);
                const float den = (mu1sq + mu2sq + C1) * (s1 + s2 + C2) + 1e-12f;
                ssim_acc += __fdividef(num, den);
            }
        }
    }

    // block reduction
    __shared__ float red[8];
#pragma unroll
    for (int o = 16; o; o >>= 1)
        ssim_acc += __shfl_down_sync(0xffffffffu, ssim_acc, o);
    if ((threadIdx.x & 31) == 0) red[threadIdx.x >> 5] = ssim_acc;
    __syncthreads();
    if (threadIdx.x == 0) {
        float s = 0.f;
#pragma unroll
        for (int k = 0; k < 8; k++) s += red[k];
        g_ssim_part[blockIdx.x + 200 * blockIdx.y] = s;
    }
}

// ---------------------------------------------------------------------------
// Final: reduce the partial arrays (8000 + 1600 floats) and combine.
// ---------------------------------------------------------------------------
__global__ __launch_bounds__(256) void k_final(float* __restrict__ out) {
    const int tid = threadIdx.x;
    double l1 = 0.0, ss = 0.0;
    for (int i = tid; i < K1_BLOCKS; i += 256) l1 += (double)g_l1_part[i];
    for (int i = tid; i < K2_BLOCKS; i += 256) ss += (double)g_ssim_part[i];

    __shared__ double rl[8], rs[8];
#pragma unroll
    for (int o = 16; o; o >>= 1) {
        l1 += __shfl_down_sync(0xffffffffu, l1, o);
        ss += __shfl_down_sync(0xffffffffu, ss, o);
    }
    if ((tid & 31) == 0) { rl[tid >> 5] = l1; rs[tid >> 5] = ss; }
    __syncthreads();
    if (tid == 0) {
        double a = 0.0, b = 0.0;
#pragma unroll
        for (int k = 0; k < 8; k++) { a += rl[k]; b += rs[k]; }
        const double inv = 1.0 / (double)NTOT;
        out[0] = (float)(0.7 * (a * inv) + 0.3 * (1.0 - b * inv));
    }
}

extern "C" void kernel_launch(void* const* d_in, const int* in_sizes, int n_in,
                              void* d_out, int out_size)
{
    const float* pred = (const float*)d_in[0];
    const float* tgt  = (const float*)d_in[1];
    float* out = (float*)d_out;

    dim3 g1(5, 5, 2 * DVOL);          // w-tiles, h-tiles, n*d
    k_blur_wh<<<g1, 256>>>(pred, tgt);

    dim3 g2((2 * HWS) / 256, 8);      // 200 x 8
    k_blur_d_ssim<<<g2, 256>>>();

    k_final<<<1, 256>>>(out);
}

// round 5
// speedup vs baseline: 1.0084x; 1.0084x over previous
#include <cuda_runtime.h>
#include <cuda_fp16.h>

// Problem constants
#define DVOL 160
#define HWS  25600            // 160*160
#define VOL  4096000          // 160^3
#define NTOT 8192000          // 2 * 160^3

// Fused-kernel tiling
#define TH   16               // output tile height
#define TW   32               // output tile width
#define RH   26               // raw rows (TH + 10)
#define RW   42               // raw cols (TW + 10)
#define RP   45               // smem pitch (odd vs 32 banks)
#define NPX  (RH * RW)        // 1092
#define DSEG 40               // depth per block
#define NDSEG 4
#define ITERS (DSEG + 10)     // 50 slices walked
#define NBLK 400              // 5 * 10 * 8

__device__ float g_l1p[NBLK];
__device__ float g_ssp[NBLK];

// Gaussian weights (size 11, sigma 1.5, normalized) as literals (FFMA-imm).
#define GW_INIT {0.00102838f, 0.00759876f, 0.03600078f, 0.10936070f, \
                 0.21300554f, 0.26601172f, 0.21300554f, 0.10936070f, \
                 0.03600078f, 0.00759876f, 0.00102838f}

// Dynamic smem layout (bytes):
//   raw   : 5 planes [RH][RP] float          at 0        (23400 -> pad 23424)
//   hst   : 5 planes [TH][RP] float          at 23424    (14400)
//   ringA : [11][TH][TW] uint2 (c0c1,c2c3)   at 37824    (45056)
//   ringB : [11][TH][TW] uint  (c4)          at 82880    (22528)
//   red   : 16 float                         at 105408   (64)
#define SM_RAW   0
#define SM_HST   23424
#define SM_RINGA 37824
#define SM_RINGB 82880
#define SM_RED   105408
#define SM_TOTAL 105472

__global__ __launch_bounds__(256, 2) void k_fused(
    const float* __restrict__ pred, const float* __restrict__ tgt)
{
    extern __shared__ char smem[];
    float    (*raw)[RH][RP]   = (float (*)[RH][RP])(smem + SM_RAW);
    float    (*hst)[TH][RP]   = (float (*)[TH][RP])(smem + SM_HST);
    uint2    (*ringA)[TH][TW] = (uint2 (*)[TH][TW])(smem + SM_RINGA);
    unsigned (*ringB)[TH][TW] = (unsigned (*)[TH][TW])(smem + SM_RINGB);
    float*   red              = (float*)(smem + SM_RED);

    const float GW[11] = GW_INIT;
    __half2 gw2[11];
#pragma unroll
    for (int j = 0; j < 11; j++) gw2[j] = __float2half2_rn(GW[j]);

    const int tid = threadIdx.x;
    const int w0 = blockIdx.x * TW;
    const int h0 = blockIdx.y * TH;
    const int z  = blockIdx.z;              // n*4 + dseg
    const int n  = z >> 2;
    const int dstart = (z & 3) * DSEG;
    const int dend   = dstart + DSEG;
    const int base   = n * VOL;

    float pv[5], tv[5];
    float l1 = 0.f, ssim_acc = 0.f;

    // ---- prefetch first raw slice --------------------------------------
    {
        const int d = dstart - 5;
        if ((unsigned)d < 160u) {
#pragma unroll
            for (int k = 0; k < 5; k++) {
                const int i = tid + (k << 8);
                if (i < NPX) {
                    const int r = i / RW, c = i - r * RW;
                    const int gh = h0 - 5 + r, gw = w0 - 5 + c;
                    const bool ok = (unsigned)gh < 160u && (unsigned)gw < 160u;
                    const int idx = base + d * HWS + gh * DVOL + gw;
                    pv[k] = ok ? pred[idx] : 0.f;
                    tv[k] = ok ? tgt[idx] : 0.f;
                }
            }
        }
    }

    for (int it = 0; it < ITERS; it++) {
        const int d = dstart - 5 + it;
        const bool dv = (unsigned)d < 160u;
        const int slot = (d + 22) % 11;

        // ---- store raw slice + products + L1 ---------------------------
        if (dv) {
#pragma unroll
            for (int k = 0; k < 5; k++) {
                const int i = tid + (k << 8);
                if (i < NPX) {
                    const int r = i / RW, c = i - r * RW;
                    const float p = pv[k], t = tv[k];
                    raw[0][r][c] = p;
                    raw[1][r][c] = t;
                    raw[2][r][c] = p * p;
                    raw[3][r][c] = t * t;
                    raw[4][r][c] = p * t;
                    if (r >= 5 && r < 21 && c >= 5 && c < 37 &&
                        d >= dstart && d < dend)
                        l1 += fabsf(p - t);
                }
            }
        }
        __syncthreads();   // raw ready

        // ---- H-blur: 26 rows -> 16, per (channel, col) -----------------
        if (dv && tid < 210) {                  // 210 = 5 ch * 42 cols
            const int ch = tid / RW;
            const int c  = tid - ch * RW;
            float acc[TH];
#pragma unroll
            for (int o = 0; o < TH; o++) acc[o] = 0.f;
#pragma unroll
            for (int r = 0; r < RH; r++) {
                const float v = raw[ch][r][c];
#pragma unroll
                for (int o = 0; o < TH; o++) {
                    const int j = r - o;
                    if (j >= 0 && j <= 10) acc[o] += GW[j] * v;
                }
            }
#pragma unroll
            for (int o = 0; o < TH; o++) hst[ch][o][c] = acc[o];
        }

        // ---- prefetch next raw slice (overlaps W/D + barriers) ---------
        if (it + 1 < ITERS) {
            const int dn = d + 1;
            if ((unsigned)dn < 160u) {
#pragma unroll
                for (int k = 0; k < 5; k++) {
                    const int i = tid + (k << 8);
                    if (i < NPX) {
                        const int r = i / RW, c = i - r * RW;
                        const int gh = h0 - 5 + r, gw = w0 - 5 + c;
                        const bool ok = (unsigned)gh < 160u && (unsigned)gw < 160u;
                        const int idx = base + dn * HWS + gh * DVOL + gw;
                        pv[k] = ok ? pred[idx] : 0.f;
                        tv[k] = ok ? tgt[idx] : 0.f;
                    }
                }
            }
        }
        __syncthreads();   // hst ready

        // ---- W-blur: 42 cols -> 32, pack fp16 into ring ----------------
        {
            const int h  = tid >> 4;
            const int wg = tid & 15;
            if (dv) {
                float acc[2][5];
#pragma unroll
                for (int o = 0; o < 2; o++)
#pragma unroll
                    for (int ch = 0; ch < 5; ch++) acc[o][ch] = 0.f;
#pragma unroll
                for (int j = 0; j < 12; j++) {
                    const int c = wg * 2 + j;
                    float v[5];
#pragma unroll
                    for (int ch = 0; ch < 5; ch++) v[ch] = hst[ch][h][c];
#pragma unroll
                    for (int o = 0; o < 2; o++) {
                        const int jj = j - o;
                        if (jj >= 0 && jj <= 10) {
#pragma unroll
                            for (int ch = 0; ch < 5; ch++)
                                acc[o][ch] += GW[jj] * v[ch];
                        }
                    }
                }
#pragma unroll
                for (int o = 0; o < 2; o++) {
                    const int w = wg * 2 + o;
                    const __half2 c01 = __floats2half2_rn(acc[o][0], acc[o][1]);
                    const __half2 c23 = __floats2half2_rn(acc[o][2], acc[o][3]);
                    const __half2 c4  = __floats2half2_rn(acc[o][4], 0.f);
                    uint2 va;
                    va.x = *(const unsigned*)&c01;
                    va.y = *(const unsigned*)&c23;
                    ringA[slot][h][w] = va;
                    ringB[slot][h][w] = *(const unsigned*)&c4;
                }
            } else {
#pragma unroll
                for (int o = 0; o < 2; o++) {
                    const int w = wg * 2 + o;
                    ringA[slot][h][w] = make_uint2(0u, 0u);
                    ringB[slot][h][w] = 0u;
                }
            }
        }
        __syncthreads();   // ring slot ready

        // ---- D-blur + SSIM at lag 5 ------------------------------------
        const int od = d - 5;
        if (od >= dstart && od < dend) {
#pragma unroll
            for (int e = 0; e < 2; e++) {
                const int px = tid + (e << 8);
                const int h = px >> 5, w = px & 31;
                __half2 a01 = __float2half2_rn(0.f);
                __half2 a23 = a01, a4 = a01;
                int s = slot + 1;                // slot of depth d-10
#pragma unroll
                for (int j = 0; j < 11; j++) {
                    if (s >= 11) s -= 11;
                    const uint2 va = ringA[s][h][w];
                    const unsigned vb = ringB[s][h][w];
                    a01 = __hfma2(gw2[j], *(const __half2*)&va.x, a01);
                    a23 = __hfma2(gw2[j], *(const __half2*)&va.y, a23);
                    a4  = __hfma2(gw2[j], *(const __half2*)&vb,  a4);
                    s++;
                }
                const float mu1 = __low2float(a01);
                const float mu2 = __high2float(a01);
                const float e11 = __low2float(a23);
                const float e22 = __high2float(a23);
                const float e12 = __low2float(a4);
                const float mu1sq = mu1 * mu1;
                const float mu2sq = mu2 * mu2;
                const float mu12  = mu1 * mu2;
                const float s1  = e11 - mu1sq;
                const float s2  = e22 - mu2sq;
                const float s12 = e12 - mu12;
                const float C1 = 1e-4f, C2 = 9e-4f;
                const float num = (2.f * mu12 + C1) * (2.f * s12 + C2);
                const float den = (mu1sq + mu2sq + C1) * (s1 + s2 + C2) + 1e-12f;
                ssim_acc += __fdividef(num, den);
            }
        }
    }

    // ---- block reduction of l1 and ssim --------------------------------
#pragma unroll
    for (int o = 16; o; o >>= 1) {
        l1       += __shfl_down_sync(0xffffffffu, l1, o);
        ssim_acc += __shfl_down_sync(0xffffffffu, ssim_acc, o);
    }
    if ((tid & 31) == 0) {
        red[tid >> 5] = l1;
        red[8 + (tid >> 5)] = ssim_acc;
    }
    __syncthreads();
    if (tid == 0) {
        float a = 0.f, b = 0.f;
#pragma unroll
        for (int k = 0; k < 8; k++) { a += red[k]; b += red[8 + k]; }
        const int bid = blockIdx.x + 5 * (blockIdx.y + 10 * blockIdx.z);
        g_l1p[bid] = a;
        g_ssp[bid] = b;
    }
}

// ---------------------------------------------------------------------------
// Final: reduce the partial arrays (400 + 400 floats) and combine.
// ---------------------------------------------------------------------------
__global__ __launch_bounds__(256) void k_final(float* __restrict__ out) {
    const int tid = threadIdx.x;
    double l1 = 0.0, ss = 0.0;
    for (int i = tid; i < NBLK; i += 256) {
        l1 += (double)g_l1p[i];
        ss += (double)g_ssp[i];
    }
    __shared__ double rl[8], rs[8];
#pragma unroll
    for (int o = 16; o; o >>= 1) {
        l1 += __shfl_down_sync(0xffffffffu, l1, o);
        ss += __shfl_down_sync(0xffffffffu, ss, o);
    }
    if ((tid & 31) == 0) { rl[tid >> 5] = l1; rs[tid >> 5] = ss; }
    __syncthreads();
    if (tid == 0) {
        double a = 0.0, b = 0.0;
#pragma unroll
        for (int k = 0; k < 8; k++) { a += rl[k]; b += rs[k]; }
        const double inv = 1.0 / (double)NTOT;
        out[0] = (float)(0.7 * (a * inv) + 0.3 * (1.0 - b * inv));
    }
}

extern "C" void kernel_launch(void* const* d_in, const int* in_sizes, int n_in,
                              void* d_out, int out_size)
{
    const float* pred = (const float*)d_in[0];
    const float* tgt  = (const float*)d_in[1];
    float* out = (float*)d_out;

    cudaFuncSetAttribute(k_fused,
                         cudaFuncAttributeMaxDynamicSharedMemorySize, SM_TOTAL);

    dim3 g(5, 10, 8);                 // wtiles, htiles, n*4 + dseg
    k_fused<<<g, 256, SM_TOTAL>>>(pred, tgt);
    k_final<<<1, 256>>>(out);
}

// round 6
// speedup vs baseline: 1.2269x; 1.2167x over previous
#include <cuda_runtime.h>
#include <cuda_fp16.h>

// Problem constants
#define DVOL 160
#define HWS  25600            // 160*160
#define VOL  4096000          // 160^3
#define NTOT 8192000          // 2 * 160^3

#define K1_BLOCKS 8000        // 5*5*320
#define K2_BLOCKS 1600        // 200*8
#define DSEG 20               // depth segment length in k2

// Packed fp16 intermediates:
//   g01[idx] = half2(blur(p),   blur(t))
//   g23[idx] = half2(blur(p*p), blur(t*t))
//   g4 [idx] = half (blur(p*t))
__device__ __half2 g01[NTOT];
__device__ __half2 g23[NTOT];
__device__ __half  g4[NTOT];
__device__ float g_l1_part[K1_BLOCKS];
__device__ float g_ssim_part[K2_BLOCKS];

// Gaussian weights (size 11, sigma 1.5, normalized) as literals so ptxas
// emits FFMA-imm (rt_SMSP=1 instead of 2).
#define GW_INIT {0.00102838f, 0.00759876f, 0.03600078f, 0.10936070f, \
                 0.21300554f, 0.26601172f, 0.21300554f, 0.10936070f, \
                 0.03600078f, 0.00759876f, 0.00102838f}

// ---------------------------------------------------------------------------
// Kernel 1: per (n,d) slice, fused W-blur + H-blur of the 5 product channels,
// 32x32 output tiles. Phase A identical to the proven R2 version; phase B
// blurs channel PAIRS in float2 rings and emits packed half2 outputs.
// ---------------------------------------------------------------------------
__global__ __launch_bounds__(256) void k_blur_wh(
    const float* __restrict__ pred, const float* __restrict__ tgt)
{
    __shared__ float rp[42][45];          // raw pred tile (pitch 45)
    __shared__ float rt[42][45];          // raw target tile
    __shared__ float2 stP[2][42][33];     // W-blurred pairs (c0,c1), (c2,c3)
    __shared__ float  stS[42][33];        // W-blurred c4
    __shared__ float red[8];

    const float GW[11] = GW_INIT;

    const int bz = blockIdx.z;            // n*160 + d
    const int n  = bz / DVOL;
    const int d  = bz % DVOL;
    const int h0 = blockIdx.y * 32;
    const int w0 = blockIdx.x * 32;
    const int base = n * VOL + d * HWS;
    const int tid = threadIdx.x;

    // --- load raw 42x42 halo region (zero padded) -------------------------
    for (int i = tid; i < 42 * 42; i += 256) {
        const int r = i / 42, c = i % 42;
        const int gh = h0 - 5 + r;
        const int gw = w0 - 5 + c;
        float p = 0.f, t = 0.f;
        if ((unsigned)gh < 160u && (unsigned)gw < 160u) {
            const int idx = base + gh * DVOL + gw;
            p = pred[idx];
            t = tgt[idx];
        }
        rp[r][c] = p;
        rt[r][c] = t;
    }
    __syncthreads();

    // --- L1 partial over the 32x32 interior -------------------------------
    float l1 = 0.f;
    for (int i = tid; i < 1024; i += 256) {
        const int hh = i >> 5, ww = i & 31;
        l1 += fabsf(rp[5 + hh][5 + ww] - rt[5 + hh][5 + ww]);
    }

    // --- phase A: blur along W with register rings ------------------------
    // thread = (row r in 0..41, col-group g in 0..5), each group covers 6 cols
    if (tid < 252) {
        const int g = tid / 42;
        const int r = tid - 42 * g;
        const int c0 = g * 6;

        float qp[11], qt[11], qpp[11], qtt[11], qpt[11];
#pragma unroll
        for (int k = 0; k < 10; k++) {
            const float p = rp[r][c0 + k];
            const float t = rt[r][c0 + k];
            qp[k] = p; qt[k] = t;
            qpp[k] = p * p; qtt[k] = t * t; qpt[k] = p * t;
        }
#pragma unroll
        for (int s = 0; s < 6; s++) {
            const int c = c0 + s;
            if (c < 32) {
                const float p = rp[r][c + 10];
                const float t = rt[r][c + 10];
                const int sl = (s + 10) % 11;
                qp[sl] = p; qt[sl] = t;
                qpp[sl] = p * p; qtt[sl] = t * t; qpt[sl] = p * t;
                float a0 = 0.f, a1 = 0.f, a2 = 0.f, a3 = 0.f, a4 = 0.f;
#pragma unroll
                for (int j = 0; j < 11; j++) {
                    const int q = (s + j) % 11;
                    const float w = GW[j];
                    a0 += w * qp[q];
                    a1 += w * qt[q];
                    a2 += w * qpp[q];
                    a3 += w * qtt[q];
                    a4 += w * qpt[q];
                }
                stP[0][r][c] = make_float2(a0, a1);
                stP[1][r][c] = make_float2(a2, a3);
                stS[r][c] = a4;
            }
        }
    }

    // reduce L1 (warp shuffles, then smem) — overlaps with phase A compute
#pragma unroll
    for (int o = 16; o; o >>= 1) l1 += __shfl_down_sync(0xffffffffu, l1, o);
    if ((tid & 31) == 0) red[tid >> 5] = l1;

    __syncthreads();   // stP/stS ready + red ready

    if (tid == 0) {
        float s = 0.f;
#pragma unroll
        for (int k = 0; k < 8; k++) s += red[k];
        const int bidlin = blockIdx.x + 5 * (blockIdx.y + 5 * blockIdx.z);
        g_l1_part[bidlin] = s;
    }

    // --- phase B: blur along H (pairs), pack half2, store -----------------
    // thread = (pair pp in 0..2, col ww in 0..31)
    if (tid < 96) {
        const int pp = tid >> 5;
        const int ww = tid & 31;
        const int obase = base + h0 * DVOL + w0 + ww;

        if (pp < 2) {
            float2 rb[11];
#pragma unroll
            for (int k = 0; k < 10; k++) rb[k] = stP[pp][k][ww];
            __half2* __restrict__ out = (pp == 0) ? g01 : g23;
#pragma unroll
            for (int hh = 0; hh < 32; hh++) {
                rb[(hh + 10) % 11] = stP[pp][hh + 10][ww];
                float ax = 0.f, ay = 0.f;
#pragma unroll
                for (int j = 0; j < 11; j++) {
                    const int q = (hh + j) % 11;
                    ax += GW[j] * rb[q].x;
                    ay += GW[j] * rb[q].y;
                }
                out[obase + hh * DVOL] = __floats2half2_rn(ax, ay);
            }
        } else {
            float rb[11];
#pragma unroll
            for (int k = 0; k < 10; k++) rb[k] = stS[k][ww];
#pragma unroll
            for (int hh = 0; hh < 32; hh++) {
                rb[(hh + 10) % 11] = stS[hh + 10][ww];
                float a = 0.f;
#pragma unroll
                for (int j = 0; j < 11; j++) a += GW[j] * rb[(hh + j) % 11];
                g4[obase + hh * DVOL] = __float2half_rn(a);
            }
        }
    }
}

// ---------------------------------------------------------------------------
// Kernel 2: blur along D with half2 rings (HFMA2 pairs + scalar c4), SSIM
// map, per-block reduction. grid: (200, 8) — 8 depth segments of 20.
// ---------------------------------------------------------------------------
__global__ __launch_bounds__(256) void k_blur_d_ssim()
{
    const float GW[11] = GW_INIT;
    __half2 gw2[11];
#pragma unroll
    for (int j = 0; j < 11; j++) gw2[j] = __float2half2_rn(GW[j]);

    const int col = blockIdx.x * 256 + threadIdx.x;   // 0..51199
    const int n  = col / HWS;
    const int hw = col - n * HWS;
    const int dstart = blockIdx.y * DSEG;
    const int base = n * VOL + hw;

    const __half2 hz = __float2half2_rn(0.f);
    __half2 r01[11], r23[11];
    float r4[11];
#pragma unroll
    for (int k = 0; k < 11; k++) { r01[k] = hz; r23[k] = hz; r4[k] = 0.f; }

    // preload depths dstart-5 .. dstart+4 into slots 0..9
#pragma unroll
    for (int k = 0; k < 10; k++) {
        const int dep = dstart - 5 + k;
        if (dep >= 0) {
            const int idx = base + dep * HWS;
            r01[k] = g01[idx];
            r23[k] = g23[idx];
            r4[k]  = __half2float(g4[idx]);
        }
    }

    float ssim_acc = 0.f;
    for (int s0 = 0; s0 < 22; s0 += 11) {
#pragma unroll
        for (int u = 0; u < 11; u++) {
            const int s = s0 + u;
            if (s < DSEG) {
                const int dep = dstart + s + 5;
                const int sl = (u + 10) % 11;
                if (dep < DVOL) {
                    const int idx = base + dep * HWS;
                    r01[sl] = g01[idx];
                    r23[sl] = g23[idx];
                    r4[sl]  = __half2float(g4[idx]);
                } else {
                    r01[sl] = hz; r23[sl] = hz; r4[sl] = 0.f;
                }
                __half2 m = hz, e = hz;
                float e12 = 0.f;
#pragma unroll
                for (int j = 0; j < 11; j++) {
                    const int q = (u + j) % 11;
                    m = __hfma2(gw2[j], r01[q], m);
                    e = __hfma2(gw2[j], r23[q], e);
                    e12 += GW[j] * r4[q];
                }
                const float2 mu = __half22float2(m);
                const float2 ev = __half22float2(e);
                const float mu1sq = mu.x * mu.x;
                const float mu2sq = mu.y * mu.y;
                const float mu12  = mu.x * mu.y;
                const float s1  = ev.x - mu1sq;
                const float s2  = ev.y - mu2sq;
                const float s12 = e12 - mu12;
                const float C1 = 1e-4f, C2 = 9e-4f;
                const float num = (2.f * mu12 + C1) * (2.f * s12 + C2);
                const float den = (mu1sq + mu2sq + C1) * (s1 + s2 + C2) + 1e-12f;
                ssim_acc += __fdividef(num, den);
            }
        }
    }

    // block reduction
    __shared__ float red[8];
#pragma unroll
    for (int o = 16; o; o >>= 1)
        ssim_acc += __shfl_down_sync(0xffffffffu, ssim_acc, o);
    if ((threadIdx.x & 31) == 0) red[threadIdx.x >> 5] = ssim_acc;
    __syncthreads();
    if (threadIdx.x == 0) {
        float s = 0.f;
#pragma unroll
        for (int k = 0; k < 8; k++) s += red[k];
        g_ssim_part[blockIdx.x + 200 * blockIdx.y] = s;
    }
}

// ---------------------------------------------------------------------------
// Final: reduce the partial arrays (8000 + 1600 floats) and combine.
// ---------------------------------------------------------------------------
__global__ __launch_bounds__(256) void k_final(float* __restrict__ out) {
    const int tid = threadIdx.x;
    double l1 = 0.0, ss = 0.0;
    for (int i = tid; i < K1_BLOCKS; i += 256) l1 += (double)g_l1_part[i];
    for (int i = tid; i < K2_BLOCKS; i += 256) ss += (double)g_ssim_part[i];

    __shared__ double rl[8], rs[8];
#pragma unroll
    for (int o = 16; o; o >>= 1) {
        l1 += __shfl_down_sync(0xffffffffu, l1, o);
        ss += __shfl_down_sync(0xffffffffu, ss, o);
    }
    if ((tid & 31) == 0) { rl[tid >> 5] = l1; rs[tid >> 5] = ss; }
    __syncthreads();
    if (tid == 0) {
        double a = 0.0, b = 0.0;
#pragma unroll
        for (int k = 0; k < 8; k++) { a += rl[k]; b += rs[k]; }
        const double inv = 1.0 / (double)NTOT;
        out[0] = (float)(0.7 * (a * inv) + 0.3 * (1.0 - b * inv));
    }
}

extern "C" void kernel_launch(void* const* d_in, const int* in_sizes, int n_in,
                              void* d_out, int out_size)
{
    const float* pred = (const float*)d_in[0];
    const float* tgt  = (const float*)d_in[1];
    float* out = (float*)d_out;

    dim3 g1(5, 5, 2 * DVOL);          // w-tiles, h-tiles, n*d
    k_blur_wh<<<g1, 256>>>(pred, tgt);

    dim3 g2((2 * HWS) / 256, 8);      // 200 x 8
    k_blur_d_ssim<<<g2, 256>>>();

    k_final<<<1, 256>>>(out);
}

// round 7
// speedup vs baseline: 1.2419x; 1.0122x over previous
#include <cuda_runtime.h>
#include <cuda_fp16.h>

// Problem constants
#define DVOL 160
#define HWS  25600            // 160*160
#define VOL  4096000          // 160^3
#define NTOT 8192000          // 2 * 160^3

#define K1_BLOCKS 8000        // 5*5*320
#define K2_BLOCKS 800         // 100*8
#define DSEG 20               // depth segment length in k2

// Packed fp16 intermediates:
//   g01[idx] = half2(blur(p),   blur(t))
//   g23[idx] = half2(blur(p*p), blur(t*t))
//   g4 [idx] = half (blur(p*t))
__device__ __half2 g01[NTOT];
__device__ __half2 g23[NTOT];
__device__ __half  g4[NTOT];
__device__ float g_l1_part[K1_BLOCKS];
__device__ float g_ssim_part[K2_BLOCKS];

// Gaussian weights (size 11, sigma 1.5, normalized).
#define GW_INIT {0.00102838f, 0.00759876f, 0.03600078f, 0.10936070f, \
                 0.21300554f, 0.26601172f, 0.21300554f, 0.10936070f, \
                 0.03600078f, 0.00759876f, 0.00102838f}

// ---- packed f32x2 helpers (Blackwell FFMA2 path, PTX-only) ---------------
typedef unsigned long long u64;

__device__ __forceinline__ u64 ffma2(u64 a, u64 b, u64 c) {
    u64 r;
    asm("fma.rn.f32x2 %0, %1, %2, %3;" : "=l"(r) : "l"(a), "l"(b), "l"(c));
    return r;
}
__device__ __forceinline__ u64 fmul2(u64 a, u64 b) {
    u64 r;
    asm("mul.rn.f32x2 %0, %1, %2;" : "=l"(r) : "l"(a), "l"(b));
    return r;
}
__device__ __forceinline__ u64 pack2(float lo, float hi) {
    u64 r;
    asm("mov.b64 %0, {%1, %2};"
        : "=l"(r) : "r"(__float_as_uint(lo)), "r"(__float_as_uint(hi)));
    return r;
}
__device__ __forceinline__ float2 unpack2(u64 v) {
    unsigned lo, hi;
    asm("mov.b64 {%0, %1}, %2;" : "=r"(lo), "=r"(hi) : "l"(v));
    return make_float2(__uint_as_float(lo), __uint_as_float(hi));
}

// ---------------------------------------------------------------------------
// Kernel 1: per (n,d) slice, fused W-blur + H-blur of the 5 product channels,
// 32x32 output tiles, f32x2-packed math, packed fp16 outputs + L1 partial.
// ---------------------------------------------------------------------------
__global__ __launch_bounds__(256) void k_blur_wh(
    const float* __restrict__ pred, const float* __restrict__ tgt)
{
    __shared__ u64 rpt[42][45];           // raw (p,t) packed; 8B-stride 45 mod 16 = 13
    __shared__ u64 stP[2][42][33];        // W-blurred pairs (p,t), (pp,tt)
    __shared__ float stS[42][33];         // W-blurred pt
    __shared__ float red[8];

    const float GW[11] = GW_INIT;
    u64 w2[11];
#pragma unroll
    for (int j = 0; j < 11; j++) w2[j] = pack2(GW[j], GW[j]);

    const int bz = blockIdx.z;            // n*160 + d
    const int n  = bz / DVOL;
    const int d  = bz % DVOL;
    const int h0 = blockIdx.y * 32;
    const int w0 = blockIdx.x * 32;
    const int base = n * VOL + d * HWS;
    const int tid = threadIdx.x;

    // --- load raw 42x42 halo region (zero padded), incremental indexing ---
    {
        int r = tid / 42;
        int c = tid - r * 42;
        while (r < 42) {
            const int gh = h0 - 5 + r;
            const int gw = w0 - 5 + c;
            float p = 0.f, t = 0.f;
            if ((unsigned)gh < 160u && (unsigned)gw < 160u) {
                const int idx = base + gh * DVOL + gw;
                p = pred[idx];
                t = tgt[idx];
            }
            rpt[r][c] = pack2(p, t);
            r += 6; c += 4;                  // advance by 256 = 6*42 + 4
            if (c >= 42) { c -= 42; r += 1; }
        }
    }
    __syncthreads();

    // --- L1 partial over the 32x32 interior -------------------------------
    float l1 = 0.f;
#pragma unroll
    for (int k = 0; k < 4; k++) {
        const int i = tid + (k << 8);
        const int hh = i >> 5, ww = i & 31;
        const float2 v = unpack2(rpt[5 + hh][5 + ww]);
        l1 += fabsf(v.x - v.y);
    }

    // --- phase A: blur along W, packed rings -------------------------------
    // thread = (row r in 0..41, col-group g in 0..5), each group covers 6 cols
    if (tid < 252) {
        const int g = tid / 42;
        const int r = tid - 42 * g;
        const int c0 = g * 6;

        u64 q01[11];
        float q4[11];
#pragma unroll
        for (int k = 0; k < 10; k++) {
            const u64 v = rpt[r][c0 + k];
            q01[k] = v;
            const float2 f = unpack2(v);
            q4[k] = f.x * f.y;
        }
#pragma unroll
        for (int s = 0; s < 6; s++) {
            const int c = c0 + s;
            if (c < 32) {
                const u64 v = rpt[r][c + 10];
                const int sl = (s + 10) % 11;
                q01[sl] = v;
                {
                    const float2 f = unpack2(v);
                    q4[sl] = f.x * f.y;
                }
                u64 a01 = 0ull, a23 = 0ull;
                float a4 = 0.f;
#pragma unroll
                for (int j = 0; j < 11; j++) {
                    const int q = (s + j) % 11;
                    const u64 x = q01[q];
                    a01 = ffma2(x, w2[j], a01);
                    a23 = ffma2(fmul2(x, x), w2[j], a23);
                    a4 += GW[j] * q4[q];
                }
                stP[0][r][c] = a01;
                stP[1][r][c] = a23;
                stS[r][c] = a4;
            }
        }
    }

    // reduce L1 (warp shuffles, then smem) — overlaps with phase A compute
#pragma unroll
    for (int o = 16; o; o >>= 1) l1 += __shfl_down_sync(0xffffffffu, l1, o);
    if ((tid & 31) == 0) red[tid >> 5] = l1;

    __syncthreads();   // stP/stS ready + red ready

    if (tid == 0) {
        float s = 0.f;
#pragma unroll
        for (int k = 0; k < 8; k++) s += red[k];
        const int bidlin = blockIdx.x + 5 * (blockIdx.y + 5 * blockIdx.z);
        g_l1_part[bidlin] = s;
    }

    // --- phase B: blur along H (packed pairs), pack half2, store ----------
    // thread = (pair pp in 0..2, col ww in 0..31)
    if (tid < 96) {
        const int pp = tid >> 5;
        const int ww = tid & 31;
        const int obase = base + h0 * DVOL + w0 + ww;

        if (pp < 2) {
            u64 rb[11];
#pragma unroll
            for (int k = 0; k < 10; k++) rb[k] = stP[pp][k][ww];
            __half2* __restrict__ out = (pp == 0) ? g01 : g23;
#pragma unroll
            for (int hh = 0; hh < 32; hh++) {
                rb[(hh + 10) % 11] = stP[pp][hh + 10][ww];
                u64 a = 0ull;
#pragma unroll
                for (int j = 0; j < 11; j++)
                    a = ffma2(rb[(hh + j) % 11], w2[j], a);
                const float2 f = unpack2(a);
                out[obase + hh * DVOL] = __floats2half2_rn(f.x, f.y);
            }
        } else {
            float rb[11];
#pragma unroll
            for (int k = 0; k < 10; k++) rb[k] = stS[k][ww];
#pragma unroll
            for (int hh = 0; hh < 32; hh++) {
                rb[(hh + 10) % 11] = stS[hh + 10][ww];
                float a = 0.f;
#pragma unroll
                for (int j = 0; j < 11; j++) a += GW[j] * rb[(hh + j) % 11];
                g4[obase + hh * DVOL] = __float2half_rn(a);
            }
        }
    }
}

// ---------------------------------------------------------------------------
// Kernel 2: blur along D, 2 adjacent columns per thread (uint2 loads, 2x MLP),
// half2 rings + HFMA2, SSIM map, per-block reduction. grid: (100, 8).
// ---------------------------------------------------------------------------
__global__ __launch_bounds__(256) void k_blur_d_ssim()
{
    __half2 gw2[11];
    {
        const float GW[11] = GW_INIT;
#pragma unroll
        for (int j = 0; j < 11; j++) gw2[j] = __float2half2_rn(GW[j]);
    }

    const int pairidx = blockIdx.x * 256 + threadIdx.x;   // 0..25599
    const int n  = pairidx / (HWS / 2);
    const int hw = (pairidx - n * (HWS / 2)) * 2;
    const int dstart = blockIdx.y * DSEG;
    const int base = n * VOL + hw;

    uint2 r01[11], r23[11];
    unsigned r4[11];
#pragma unroll
    for (int k = 0; k < 11; k++) {
        r01[k] = make_uint2(0u, 0u);
        r23[k] = make_uint2(0u, 0u);
        r4[k] = 0u;
    }

    // preload depths dstart-5 .. dstart+4 into slots 0..9
#pragma unroll
    for (int k = 0; k < 10; k++) {
        const int dep = dstart - 5 + k;
        if (dep >= 0) {
            const int idx = base + dep * HWS;
            r01[k] = *(const uint2*)(g01 + idx);
            r23[k] = *(const uint2*)(g23 + idx);
            r4[k]  = *(const unsigned*)(g4 + idx);
        }
    }

    const __half2 hz = __float2half2_rn(0.f);
    float ssim_acc = 0.f;
    for (int s0 = 0; s0 < 22; s0 += 11) {
#pragma unroll
        for (int u = 0; u < 11; u++) {
            const int s = s0 + u;
            if (s < DSEG) {
                const int dep = dstart + s + 5;
                const int sl = (u + 10) % 11;
                if (dep < DVOL) {
                    const int idx = base + dep * HWS;
                    r01[sl] = *(const uint2*)(g01 + idx);
                    r23[sl] = *(const uint2*)(g23 + idx);
                    r4[sl]  = *(const unsigned*)(g4 + idx);
                } else {
                    r01[sl] = make_uint2(0u, 0u);
                    r23[sl] = make_uint2(0u, 0u);
                    r4[sl] = 0u;
                }
                __half2 mA = hz, mB = hz, eA = hz, eB = hz, e4 = hz;
#pragma unroll
                for (int j = 0; j < 11; j++) {
                    const int q = (u + j) % 11;
                    mA = __hfma2(gw2[j], *(const __half2*)&r01[q].x, mA);
                    mB = __hfma2(gw2[j], *(const __half2*)&r01[q].y, mB);
                    eA = __hfma2(gw2[j], *(const __half2*)&r23[q].x, eA);
                    eB = __hfma2(gw2[j], *(const __half2*)&r23[q].y, eB);
                    e4 = __hfma2(gw2[j], *(const __half2*)&r4[q],   e4);
                }
                const float2 e4f = __half22float2(e4);
#pragma unroll
                for (int cc = 0; cc < 2; cc++) {
                    const float2 mu = __half22float2(cc ? mB : mA);
                    const float2 ev = __half22float2(cc ? eB : eA);
                    const float e12 = cc ? e4f.y : e4f.x;
                    const float mu1sq = mu.x * mu.x;
                    const float mu2sq = mu.y * mu.y;
                    const float mu12  = mu.x * mu.y;
                    const float s1  = ev.x - mu1sq;
                    const float s2  = ev.y - mu2sq;
                    const float s12 = e12 - mu12;
                    const float C1 = 1e-4f, C2 = 9e-4f;
                    const float num = (2.f * mu12 + C1) * (2.f * s12 + C2);
                    const float den = (mu1sq + mu2sq + C1) * (s1 + s2 + C2) + 1e-12f;
                    ssim_acc += __fdividef(num, den);
                }
            }
        }
    }

    // block reduction
    __shared__ float red[8];
#pragma unroll
    for (int o = 16; o; o >>= 1)
        ssim_acc += __shfl_down_sync(0xffffffffu, ssim_acc, o);
    if ((threadIdx.x & 31) == 0) red[threadIdx.x >> 5] = ssim_acc;
    __syncthreads();
    if (threadIdx.x == 0) {
        float s = 0.f;
#pragma unroll
        for (int k = 0; k < 8; k++) s += red[k];
        g_ssim_part[blockIdx.x + 100 * blockIdx.y] = s;
    }
}

// ---------------------------------------------------------------------------
// Final: reduce the partial arrays (8000 + 800 floats) and combine.
// ---------------------------------------------------------------------------
__global__ __launch_bounds__(256) void k_final(float* __restrict__ out) {
    const int tid = threadIdx.x;
    double l1 = 0.0, ss = 0.0;
    for (int i = tid; i < K1_BLOCKS; i += 256) l1 += (double)g_l1_part[i];
    for (int i = tid; i < K2_BLOCKS; i += 256) ss += (double)g_ssim_part[i];

    __shared__ double rl[8], rs[8];
#pragma unroll
    for (int o = 16; o; o >>= 1) {
        l1 += __shfl_down_sync(0xffffffffu, l1, o);
        ss += __shfl_down_sync(0xffffffffu, ss, o);
    }
    if ((tid & 31) == 0) { rl[tid >> 5] = l1; rs[tid >> 5] = ss; }
    __syncthreads();
    if (tid == 0) {
        double a = 0.0, b = 0.0;
#pragma unroll
        for (int k = 0; k < 8; k++) { a += rl[k]; b += rs[k]; }
        const double inv = 1.0 / (double)NTOT;
        out[0] = (float)(0.7 * (a * inv) + 0.3 * (1.0 - b * inv));
    }
}

extern "C" void kernel_launch(void* const* d_in, const int* in_sizes, int n_in,
                              void* d_out, int out_size)
{
    const float* pred = (const float*)d_in[0];
    const float* tgt  = (const float*)d_in[1];
    float* out = (float*)d_out;

    dim3 g1(5, 5, 2 * DVOL);          // w-tiles, h-tiles, n*d
    k_blur_wh<<<g1, 256>>>(pred, tgt);

    dim3 g2(100, 8);                  // column pairs, depth segments
    k_blur_d_ssim<<<g2, 256>>>();

    k_final<<<1, 256>>>(out);
}